// round 15
// baseline (speedup 1.0000x reference)
#include <cuda_runtime.h>
#include <cuda_fp16.h>
#include <math.h>
#include <stdint.h>

#define N_TOK 8192
#define DIM   1024
#define HID   4096
#define NE    8

// dynamic smem layout (bytes). Rows are 144B (128B data + 16B pad):
// cp.async-aligned (144 = 9*16); gather words 36r+q mod 32 = 4r+q -> perfect permutation.
#define OFF_A    0          // [3][128][36] u32 = 55296 (reused as h-staging post-loop)
#define OFF_B    55296      // [3][256][36] u32 = 110592
#define OFF_AROW 165888     // 128 u32
#define OFF_BROW 166400     // 256 u32
#define SMEM_TOTAL 167424

// ======================= PTX helpers =======================
__device__ __forceinline__ uint32_t smem_u32(const void* p) {
    uint32_t a;
    asm("{ .reg .u64 t; cvta.to.shared.u64 t, %1; cvt.u32.u64 %0, t; }" : "=r"(a) : "l"(p));
    return a;
}
#define CPA16(s, g) asm volatile("cp.async.cg.shared.global [%0], [%1], 16;" :: "r"(s), "l"(g))
#define CPC()       asm volatile("cp.async.commit_group;" ::: "memory")
#define CPW(n)      asm volatile("cp.async.wait_group %0;" :: "n"(n) : "memory")

__device__ __forceinline__ void mma_f16(float* d, const uint32_t* a, const uint32_t* b) {
    asm volatile("mma.sync.aligned.m16n8k16.row.col.f32.f16.f16.f32 "
                 "{%0,%1,%2,%3},{%4,%5,%6,%7},{%8,%9},{%0,%1,%2,%3};"
                 : "+f"(d[0]), "+f"(d[1]), "+f"(d[2]), "+f"(d[3])
                 : "r"(a[0]), "r"(a[1]), "r"(a[2]), "r"(a[3]), "r"(b[0]), "r"(b[1]));
}

// ======================= device scratch =======================
__device__ int   g_count[NE];
__device__ int   g_off[NE];
__device__ int   g_tok[NE * N_TOK];
__device__ float g_gate[NE * N_TOK];
__device__ float g_ent;
__device__ float g_imp[NE];

__device__ __align__(16) __half g_xh[(size_t)N_TOK * DIM];
__device__ __align__(16) __half g_w1h[(size_t)NE * HID * DIM];   // [e][n(hid)][k(dim)]
__device__ __align__(16) __half g_w2h[(size_t)NE * DIM * HID];   // [e][n(dim)][k(hid)]
__device__ __align__(16) __half g_hh[(size_t)2 * N_TOK * HID];   // [slot][hid]

// ======================= small kernels =======================
__global__ void zero_kernel() {
    int t = threadIdx.x;
    if (t < NE) { g_count[t] = 0; g_imp[t] = 0.f; }
    if (t == 0) g_ent = 0.f;
}

__global__ void router_kernel(const float* __restrict__ x,
                              const float* __restrict__ rw,
                              const float* __restrict__ rb) {
    __shared__ float s_ent[8];
    __shared__ float s_imp[8][NE];
    int warp = threadIdx.x >> 5;
    int lane = threadIdx.x & 31;
    int t = blockIdx.x * 8 + warp;

    float acc[NE];
#pragma unroll
    for (int e = 0; e < NE; e++) acc[e] = 0.f;
    const float* xr = x + (size_t)t * DIM;
    for (int k = lane; k < DIM; k += 32) {
        float xv = xr[k];
        const float* rwk = rw + k * NE;
#pragma unroll
        for (int e = 0; e < NE; e++) acc[e] += xv * rwk[e];
    }
#pragma unroll
    for (int e = 0; e < NE; e++)
#pragma unroll
        for (int s = 16; s > 0; s >>= 1)
            acc[e] += __shfl_xor_sync(0xffffffff, acc[e], s);

    if (lane == 0) {
        float lg[NE], m = -1e30f;
#pragma unroll
        for (int e = 0; e < NE; e++) { lg[e] = acc[e] + rb[e]; m = fmaxf(m, lg[e]); }
        float p[NE], sum = 0.f;
#pragma unroll
        for (int e = 0; e < NE; e++) { p[e] = expf(lg[e] - m); sum += p[e]; }
        float inv = 1.f / sum, ent = 0.f;
#pragma unroll
        for (int e = 0; e < NE; e++) {
            float pe = p[e] * inv;
            ent -= pe * logf(fmaxf(pe, 1e-8f));
            s_imp[warp][e] = pe;
        }
        s_ent[warp] = ent;
        int e0 = 0;
#pragma unroll
        for (int e = 1; e < NE; e++) if (lg[e] > lg[e0]) e0 = e;
        int e1 = (e0 == 0) ? 1 : 0;
#pragma unroll
        for (int e = 0; e < NE; e++) if (e != e0 && lg[e] > lg[e1]) e1 = e;
        float g0 = 1.f / (1.f + expf(lg[e1] - lg[e0]));
        float g1 = 1.f - g0;
        int p0 = atomicAdd(&g_count[e0], 1);
        g_tok [e0 * N_TOK + p0] = t; g_gate[e0 * N_TOK + p0] = g0;
        int p1 = atomicAdd(&g_count[e1], 1);
        g_tok [e1 * N_TOK + p1] = t; g_gate[e1 * N_TOK + p1] = g1;
    }
    __syncthreads();
    if (threadIdx.x < NE) {
        float se = 0.f;
#pragma unroll
        for (int w = 0; w < 8; w++) se += s_imp[w][threadIdx.x];
        atomicAdd(&g_imp[threadIdx.x], se);
    }
    if (threadIdx.x == 0) {
        float se = 0.f;
#pragma unroll
        for (int w = 0; w < 8; w++) se += s_ent[w];
        atomicAdd(&g_ent, se);
    }
}

__global__ void offsets_kernel() {
    if (threadIdx.x == 0) {
        int s = 0;
#pragma unroll
        for (int e = 0; e < NE; e++) { g_off[e] = s; s += g_count[e]; }
    }
}

__global__ void convert_x_kernel(const float* __restrict__ x) {
    size_t i = ((size_t)blockIdx.x * 256 + threadIdx.x) * 4;
    float4 v = *(const float4*)(x + i);
    uint32_t p0 = (uint32_t)__half_as_ushort(__float2half_rn(v.x))
                | ((uint32_t)__half_as_ushort(__float2half_rn(v.y)) << 16);
    uint32_t p1 = (uint32_t)__half_as_ushort(__float2half_rn(v.z))
                | ((uint32_t)__half_as_ushort(__float2half_rn(v.w)) << 16);
    *(uint2*)(g_xh + i) = make_uint2(p0, p1);
}

// transpose: src [e][R][C] fp32 -> INTERNAL dst [e][C][R] fp16, 8B vector stores.
// which=0 -> g_w1h ; which=1 -> g_w2h   (never pass device globals as host args)
__global__ void transpose_convert_kernel(const float* __restrict__ src,
                                         int which, int R, int C) {
    __shared__ float t[32][33];
    __half* dh = which ? g_w2h : g_w1h;
    int e = blockIdx.z;
    int c0 = blockIdx.x * 32, r0 = blockIdx.y * 32;
    const float* s = src + (size_t)e * R * C;
    int tx = threadIdx.x & 31, ty = threadIdx.x >> 5;
#pragma unroll
    for (int i = ty; i < 32; i += 8)
        t[i][tx] = s[(size_t)(r0 + i) * C + c0 + tx];
    __syncthreads();
    int co = threadIdx.x >> 3;
    int rg = (threadIdx.x & 7) * 4;
    __half h0 = __float2half_rn(t[rg + 0][co]);
    __half h1 = __float2half_rn(t[rg + 1][co]);
    __half h2 = __float2half_rn(t[rg + 2][co]);
    __half h3 = __float2half_rn(t[rg + 3][co]);
    uint2 v;
    v.x = (uint32_t)__half_as_ushort(h0) | ((uint32_t)__half_as_ushort(h1) << 16);
    v.y = (uint32_t)__half_as_ushort(h2) | ((uint32_t)__half_as_ushort(h3) << 16);
    size_t o = (size_t)e * R * C + (size_t)(c0 + co) * R + r0 + rg;
    *(uint2*)(dh + o) = v;
}

// ======================= cp.async stage loader (K-chunk 64 = 128B/row) =======================
__device__ __forceinline__ void load_stage(
    uint32_t abase, uint32_t bbase,
    const __half* __restrict__ Ah, const __half* __restrict__ Bh,
    const uint32_t* __restrict__ arow, const uint32_t* __restrict__ brow,
    int k0, int buf)
{
    int tid = threadIdx.x;
    int row = tid >> 1, hf = tid & 1;
    uint32_t hb = (uint32_t)hf * 64u;

    // A: 128 rows x 128B; each thread 4 x 16B
    uint32_t ka = arow[row] + k0 + hf * 32;
    uint32_t da = abase + (uint32_t)buf * (128 * 144) + (uint32_t)row * 144 + hb;
    CPA16(da,      Ah + ka);
    CPA16(da + 16, Ah + ka + 8);
    CPA16(da + 32, Ah + ka + 16);
    CPA16(da + 48, Ah + ka + 24);

    // B: 256 rows x 128B; each thread 8 x 16B (two rows)
    uint32_t kb0 = brow[row]       + k0 + hf * 32;
    uint32_t kb1 = brow[row + 128] + k0 + hf * 32;
    uint32_t db = bbase + (uint32_t)buf * (256 * 144) + (uint32_t)row * 144 + hb;
    CPA16(db,      Bh + kb0);
    CPA16(db + 16, Bh + kb0 + 8);
    CPA16(db + 32, Bh + kb0 + 16);
    CPA16(db + 48, Bh + kb0 + 24);
    uint32_t db1 = db + 128 * 144;
    CPA16(db1,      Bh + kb1);
    CPA16(db1 + 16, Bh + kb1 + 8);
    CPA16(db1 + 32, Bh + kb1 + 16);
    CPA16(db1 + 48, Bh + kb1 + 24);
    CPC();
}

// ======================= GEMM mainloop: CTA 128x256, warp 64x64 =======================
// K-stage 64, 3-buffer cp.async pipeline, ONE __syncthreads per stage.
__device__ __forceinline__ void mma_mainloop(
    char* smc,
    const __half* __restrict__ Ah, const __half* __restrict__ Bh,
    const uint32_t* __restrict__ arow, const uint32_t* __restrict__ brow,
    int S, float (&acc)[4][8][4])
{
    int tid  = threadIdx.x;
    int lane = tid & 31;
    int wid  = tid >> 5;
    int wm   = wid & 1;        // 2 m-groups of 64
    int wn   = wid >> 1;       // 4 n-groups of 64
    int q    = lane & 3;
    int r4   = lane >> 2;

    uint32_t (*A)[128][36] = (uint32_t (*)[128][36])(smc + OFF_A);
    uint32_t (*B)[256][36] = (uint32_t (*)[256][36])(smc + OFF_B);
    uint32_t abase = smem_u32(&A[0][0][0]);
    uint32_t bbase = smem_u32(&B[0][0][0]);

    load_stage(abase, bbase, Ah, Bh, arow, brow, 0,  0);
    load_stage(abase, bbase, Ah, Bh, arow, brow, 64, 1);

    int bu = 0, bnx = 2;
    for (int s = 0; s < S; s++) {
        CPW(1);
        __syncthreads();
        if (s + 2 < S)
            load_stage(abase, bbase, Ah, Bh, arow, brow, (s + 2) * 64, bnx);
        else
            CPC();   // keep group accounting uniform

#pragma unroll
        for (int kc = 0; kc < 4; kc++) {
            int kq = kc * 8 + q;
            uint32_t bhf[8][2];
#pragma unroll
            for (int nt = 0; nt < 8; nt++) {
                int nb = wn * 64 + nt * 8 + r4;
                bhf[nt][0] = B[bu][nb][kq];
                bhf[nt][1] = B[bu][nb][kq + 4];
            }
#pragma unroll
            for (int mt = 0; mt < 4; mt++) {
                int ra = wm * 64 + mt * 16 + r4;
                uint32_t ah[4];
                ah[0] = A[bu][ra][kq];      ah[1] = A[bu][ra + 8][kq];
                ah[2] = A[bu][ra][kq + 4];  ah[3] = A[bu][ra + 8][kq + 4];
#pragma unroll
                for (int nt = 0; nt < 8; nt++)
                    mma_f16(acc[mt][nt], ah, bhf[nt]);
            }
        }
        bu = (bu == 2) ? 0 : bu + 1;
        bnx = (bnx == 2) ? 0 : bnx + 1;
    }
    __syncthreads();   // all compute done before smem reuse
}

// ======================= GEMM1: h = relu(x @ w1 + b1) =======================
__global__ void __launch_bounds__(256)
gemm1_mma(const float* __restrict__ b1) {
    int e = blockIdx.z;
    int ce = g_count[e];
    int m0 = blockIdx.y * 128;
    if (m0 >= ce) return;
    int n0 = blockIdx.x * 256;
    int off = g_off[e];

    extern __shared__ char smc[];
    uint32_t* s_arow = (uint32_t*)(smc + OFF_AROW);
    uint32_t* s_brow = (uint32_t*)(smc + OFF_BROW);

    int tid = threadIdx.x;
    if (tid < 128) {
        int tok = (m0 + tid < ce) ? g_tok[e * N_TOK + m0 + tid] : 0;
        s_arow[tid] = (uint32_t)tok * DIM;
    }
    s_brow[tid] = (uint32_t)(e * HID + n0 + tid) * DIM;
    __syncthreads();

    float acc[4][8][4];
#pragma unroll
    for (int i = 0; i < 4; i++)
#pragma unroll
        for (int j = 0; j < 8; j++)
#pragma unroll
            for (int k = 0; k < 4; k++) acc[i][j][k] = 0.f;

    mma_mainloop(smc, g_xh, g_w1h, s_arow, s_brow, DIM / 64, acc);

    // epilogue: bias + relu -> stage 16x64 fp16 tile in smem -> coalesced 16B stores
    int lane = tid & 31, wid = tid >> 5;
    int wm = wid & 1, wn = wid >> 1;
    int r = lane >> 2, q = lane & 3;
    __half* stg = (__half*)(smc + OFF_A) + (size_t)wid * 1152;  // 16 rows x 72
    const float* brow_b1 = b1 + e * HID + n0 + wn * 64;
    int lr2 = lane >> 1, half2 = lane & 1;

#pragma unroll
    for (int mt = 0; mt < 4; mt++) {
#pragma unroll
        for (int rh = 0; rh < 2; rh++) {
            int lr = r + rh * 8;
#pragma unroll
            for (int nt = 0; nt < 8; nt++) {
                int lc = nt * 8 + 2 * q;
                float f0 = fmaxf(acc[mt][nt][rh * 2 + 0] + brow_b1[lc],     0.f);
                float f1 = fmaxf(acc[mt][nt][rh * 2 + 1] + brow_b1[lc + 1], 0.f);
                uint32_t ph = (uint32_t)__half_as_ushort(__float2half_rn(f0))
                            | ((uint32_t)__half_as_ushort(__float2half_rn(f1)) << 16);
                *(uint32_t*)(stg + lr * 72 + lc) = ph;
            }
        }
        __syncwarp();
        int grow = wm * 64 + mt * 16 + lr2;
        if (m0 + grow < ce) {
            size_t slot = (size_t)(off + m0 + grow);
            __half* dst = g_hh + slot * HID + n0 + wn * 64 + half2 * 32;
            const __half* srcp = stg + lr2 * 72 + half2 * 32;
#pragma unroll
            for (int c = 0; c < 4; c++)
                *(uint4*)(dst + c * 8) = *(const uint4*)(srcp + c * 8);
        }
        __syncwarp();
    }
}

// ======================= GEMM2: out += gate * (h @ w2 + b2) =======================
// Two m-tiles per CTA (R13 config, best measured).
__global__ void __launch_bounds__(256)
gemm2_mma(const float* __restrict__ b2, float* __restrict__ out) {
    int e = blockIdx.z;
    int ce = g_count[e];
    int n0 = blockIdx.x * 256;
    int off = g_off[e];

    extern __shared__ char smc[];
    uint32_t* s_arow = (uint32_t*)(smc + OFF_AROW);
    uint32_t* s_brow = (uint32_t*)(smc + OFF_BROW);

    int tid = threadIdx.x;
    int lane = tid & 31, wid = tid >> 5;
    int wm = wid & 1, wn = wid >> 1;
    int r = lane >> 2, q = lane & 3;

    s_brow[tid] = (uint32_t)(e * DIM + n0 + tid) * HID;

#pragma unroll 1
    for (int mi = 0; mi < 2; mi++) {
        int m0 = (blockIdx.y * 2 + mi) * 128;
        if (m0 >= ce) break;

        __syncthreads();   // brow store (mi=0) / prior tile fully done (mi=1)
        if (tid < 128) {
            int sl = off + m0 + tid;
            if (sl > 2 * N_TOK - 1) sl = 2 * N_TOK - 1;
            s_arow[tid] = (uint32_t)sl * HID;
        }
        __syncthreads();

        float acc[4][8][4];
#pragma unroll
        for (int i = 0; i < 4; i++)
#pragma unroll
            for (int j = 0; j < 8; j++)
#pragma unroll
                for (int k = 0; k < 4; k++) acc[i][j][k] = 0.f;

        mma_mainloop(smc, g_hh, g_w2h, s_arow, s_brow, HID / 64, acc);

        // epilogue: gate-weighted atomic add
#pragma unroll
        for (int mt = 0; mt < 4; mt++) {
#pragma unroll
            for (int rh = 0; rh < 2; rh++) {
                int row = wm * 64 + mt * 16 + r + rh * 8;
                if (m0 + row >= ce) continue;
                int slot2 = e * N_TOK + m0 + row;
                int tok = g_tok[slot2];
                float gw = g_gate[slot2];
                float* ob = out + (size_t)tok * DIM;
#pragma unroll
                for (int nt = 0; nt < 8; nt++) {
                    int col = n0 + wn * 64 + nt * 8 + 2 * q;
                    float f0 = acc[mt][nt][rh * 2 + 0] + b2[e * DIM + col];
                    float f1 = acc[mt][nt][rh * 2 + 1] + b2[e * DIM + col + 1];
                    atomicAdd(ob + col,     gw * f0);
                    atomicAdd(ob + col + 1, gw * f1);
                }
            }
        }
    }
}

// ======================= aux =======================
__global__ void aux_kernel(float* __restrict__ out, int out_size) {
    if (threadIdx.x == 0 && out_size >= N_TOK * DIM + 2) {
        float ent = g_ent / (float)N_TOK;
        float lb = 0.f;
#pragma unroll
        for (int e = 0; e < NE; e++) {
            float d = g_imp[e] / (float)N_TOK - 1.f / (float)NE;
            lb += d * d;
        }
        lb /= (float)NE;
        out[N_TOK * DIM]     = ent;
        out[N_TOK * DIM + 1] = lb;
    }
}

// ======================= launch (single stream) =======================
extern "C" void kernel_launch(void* const* d_in, const int* in_sizes, int n_in,
                              void* d_out, int out_size) {
    const float* x  = (const float*)d_in[0];
    const float* rw = (const float*)d_in[1];
    const float* rb = (const float*)d_in[2];
    const float* w1 = (const float*)d_in[3];
    const float* b1 = (const float*)d_in[4];
    const float* w2 = (const float*)d_in[5];
    const float* b2 = (const float*)d_in[6];
    float* out = (float*)d_out;

    cudaFuncSetAttribute(gemm1_mma, cudaFuncAttributeMaxDynamicSharedMemorySize, SMEM_TOTAL);
    cudaFuncSetAttribute(gemm2_mma, cudaFuncAttributeMaxDynamicSharedMemorySize, SMEM_TOTAL);

    cudaMemsetAsync(d_out, 0, (size_t)out_size * sizeof(float), 0);
    zero_kernel<<<1, 32>>>();
    router_kernel<<<N_TOK / 8, 256>>>(x, rw, rb);
    offsets_kernel<<<1, 1>>>();
    convert_x_kernel<<<(N_TOK * DIM) / 1024, 256>>>(x);
    {
        dim3 g(HID / 32, DIM / 32, NE);
        transpose_convert_kernel<<<g, 256>>>(w1, 0, DIM, HID);
    }
    {
        dim3 g(DIM / 32, HID / 32, NE);
        transpose_convert_kernel<<<g, 256>>>(w2, 1, HID, DIM);
    }

    {
        dim3 g(HID / 256, N_TOK / 128, NE);
        gemm1_mma<<<g, 256, SMEM_TOTAL>>>(b1);
    }
    {
        dim3 g(DIM / 256, N_TOK / 256, NE);   // 2 m-tiles per CTA
        gemm2_mma<<<g, 256, SMEM_TOTAL>>>(b2, out);
    }
    aux_kernel<<<1, 1>>>(out, out_size);
}

// round 16
// speedup vs baseline: 1.0179x; 1.0179x over previous
#include <cuda_runtime.h>
#include <cuda_fp16.h>
#include <math.h>
#include <stdint.h>

#define N_TOK 8192
#define DIM   1024
#define HID   4096
#define NE    8

// dynamic smem layout (bytes). Rows are 80B (64B data + 16B pad):
// cp.async-aligned (80 = 5*16); 8-row gather/ldmatrix phases hit banks 20r mod 32
// = perfect permutation -> conflict-free.
#define OFF_A    0          // [3][128][20] u32 = 30720 (reused as h-staging post-loop)
#define OFF_B    30720      // [3][256][20] u32 = 61440
#define OFF_AROW 92160      // 128 u32
#define OFF_BROW 92672      // 256 u32
#define SMEM_TOTAL 93696

// ======================= PTX helpers =======================
__device__ __forceinline__ uint32_t smem_u32(const void* p) {
    uint32_t a;
    asm("{ .reg .u64 t; cvta.to.shared.u64 t, %1; cvt.u32.u64 %0, t; }" : "=r"(a) : "l"(p));
    return a;
}
#define CPA16(s, g) asm volatile("cp.async.cg.shared.global [%0], [%1], 16;" :: "r"(s), "l"(g))
#define CPC()       asm volatile("cp.async.commit_group;" ::: "memory")
#define CPW(n)      asm volatile("cp.async.wait_group %0;" :: "n"(n) : "memory")

__device__ __forceinline__ void ldsm4(uint32_t* r, uint32_t addr) {
    asm volatile("ldmatrix.sync.aligned.m8n8.x4.shared.b16 {%0,%1,%2,%3}, [%4];"
                 : "=r"(r[0]), "=r"(r[1]), "=r"(r[2]), "=r"(r[3]) : "r"(addr));
}
__device__ __forceinline__ void mma_f16(float* d, const uint32_t* a, const uint32_t* b) {
    asm volatile("mma.sync.aligned.m16n8k16.row.col.f32.f16.f16.f32 "
                 "{%0,%1,%2,%3},{%4,%5,%6,%7},{%8,%9},{%0,%1,%2,%3};"
                 : "+f"(d[0]), "+f"(d[1]), "+f"(d[2]), "+f"(d[3])
                 : "r"(a[0]), "r"(a[1]), "r"(a[2]), "r"(a[3]), "r"(b[0]), "r"(b[1]));
}

// ======================= device scratch =======================
__device__ int   g_count[NE];
__device__ int   g_off[NE];
__device__ int   g_tok[NE * N_TOK];
__device__ float g_gate[NE * N_TOK];
__device__ float g_ent;
__device__ float g_imp[NE];

__device__ __align__(16) __half g_xh[(size_t)N_TOK * DIM];
__device__ __align__(16) __half g_w1h[(size_t)NE * HID * DIM];   // [e][n(hid)][k(dim)]
__device__ __align__(16) __half g_w2h[(size_t)NE * DIM * HID];   // [e][n(dim)][k(hid)]
__device__ __align__(16) __half g_hh[(size_t)2 * N_TOK * HID];   // [slot][hid]

// ======================= small kernels =======================
__global__ void zero_kernel() {
    int t = threadIdx.x;
    if (t < NE) { g_count[t] = 0; g_imp[t] = 0.f; }
    if (t == 0) g_ent = 0.f;
}

__global__ void router_kernel(const float* __restrict__ x,
                              const float* __restrict__ rw,
                              const float* __restrict__ rb) {
    __shared__ float s_ent[8];
    __shared__ float s_imp[8][NE];
    int warp = threadIdx.x >> 5;
    int lane = threadIdx.x & 31;
    int t = blockIdx.x * 8 + warp;

    float acc[NE];
#pragma unroll
    for (int e = 0; e < NE; e++) acc[e] = 0.f;
    const float* xr = x + (size_t)t * DIM;
    for (int k = lane; k < DIM; k += 32) {
        float xv = xr[k];
        const float* rwk = rw + k * NE;
#pragma unroll
        for (int e = 0; e < NE; e++) acc[e] += xv * rwk[e];
    }
#pragma unroll
    for (int e = 0; e < NE; e++)
#pragma unroll
        for (int s = 16; s > 0; s >>= 1)
            acc[e] += __shfl_xor_sync(0xffffffff, acc[e], s);

    if (lane == 0) {
        float lg[NE], m = -1e30f;
#pragma unroll
        for (int e = 0; e < NE; e++) { lg[e] = acc[e] + rb[e]; m = fmaxf(m, lg[e]); }
        float p[NE], sum = 0.f;
#pragma unroll
        for (int e = 0; e < NE; e++) { p[e] = expf(lg[e] - m); sum += p[e]; }
        float inv = 1.f / sum, ent = 0.f;
#pragma unroll
        for (int e = 0; e < NE; e++) {
            float pe = p[e] * inv;
            ent -= pe * logf(fmaxf(pe, 1e-8f));
            s_imp[warp][e] = pe;
        }
        s_ent[warp] = ent;
        int e0 = 0;
#pragma unroll
        for (int e = 1; e < NE; e++) if (lg[e] > lg[e0]) e0 = e;
        int e1 = (e0 == 0) ? 1 : 0;
#pragma unroll
        for (int e = 0; e < NE; e++) if (e != e0 && lg[e] > lg[e1]) e1 = e;
        float g0 = 1.f / (1.f + expf(lg[e1] - lg[e0]));
        float g1 = 1.f - g0;
        int p0 = atomicAdd(&g_count[e0], 1);
        g_tok [e0 * N_TOK + p0] = t; g_gate[e0 * N_TOK + p0] = g0;
        int p1 = atomicAdd(&g_count[e1], 1);
        g_tok [e1 * N_TOK + p1] = t; g_gate[e1 * N_TOK + p1] = g1;
    }
    __syncthreads();
    if (threadIdx.x < NE) {
        float se = 0.f;
#pragma unroll
        for (int w = 0; w < 8; w++) se += s_imp[w][threadIdx.x];
        atomicAdd(&g_imp[threadIdx.x], se);
    }
    if (threadIdx.x == 0) {
        float se = 0.f;
#pragma unroll
        for (int w = 0; w < 8; w++) se += s_ent[w];
        atomicAdd(&g_ent, se);
    }
}

__global__ void offsets_kernel() {
    if (threadIdx.x == 0) {
        int s = 0;
#pragma unroll
        for (int e = 0; e < NE; e++) { g_off[e] = s; s += g_count[e]; }
    }
}

__global__ void convert_x_kernel(const float* __restrict__ x) {
    size_t i = ((size_t)blockIdx.x * 256 + threadIdx.x) * 4;
    float4 v = *(const float4*)(x + i);
    uint32_t p0 = (uint32_t)__half_as_ushort(__float2half_rn(v.x))
                | ((uint32_t)__half_as_ushort(__float2half_rn(v.y)) << 16);
    uint32_t p1 = (uint32_t)__half_as_ushort(__float2half_rn(v.z))
                | ((uint32_t)__half_as_ushort(__float2half_rn(v.w)) << 16);
    *(uint2*)(g_xh + i) = make_uint2(p0, p1);
}

// transpose: src [e][R][C] fp32 -> INTERNAL dst [e][C][R] fp16, 8B vector stores.
// which=0 -> g_w1h ; which=1 -> g_w2h   (never pass device globals as host args)
__global__ void transpose_convert_kernel(const float* __restrict__ src,
                                         int which, int R, int C) {
    __shared__ float t[32][33];
    __half* dh = which ? g_w2h : g_w1h;
    int e = blockIdx.z;
    int c0 = blockIdx.x * 32, r0 = blockIdx.y * 32;
    const float* s = src + (size_t)e * R * C;
    int tx = threadIdx.x & 31, ty = threadIdx.x >> 5;
#pragma unroll
    for (int i = ty; i < 32; i += 8)
        t[i][tx] = s[(size_t)(r0 + i) * C + c0 + tx];
    __syncthreads();
    int co = threadIdx.x >> 3;
    int rg = (threadIdx.x & 7) * 4;
    __half h0 = __float2half_rn(t[rg + 0][co]);
    __half h1 = __float2half_rn(t[rg + 1][co]);
    __half h2 = __float2half_rn(t[rg + 2][co]);
    __half h3 = __float2half_rn(t[rg + 3][co]);
    uint2 v;
    v.x = (uint32_t)__half_as_ushort(h0) | ((uint32_t)__half_as_ushort(h1) << 16);
    v.y = (uint32_t)__half_as_ushort(h2) | ((uint32_t)__half_as_ushort(h3) << 16);
    size_t o = (size_t)e * R * C + (size_t)(c0 + co) * R + r0 + rg;
    *(uint2*)(dh + o) = v;
}

// ======================= cp.async stage loader (K-chunk 32 = 64B/row) =======================
__device__ __forceinline__ void load_stage(
    uint32_t abase, uint32_t bbase,
    const __half* __restrict__ Ah, const __half* __restrict__ Bh,
    const uint32_t* __restrict__ arow, const uint32_t* __restrict__ brow,
    int k0, int buf)
{
    int tid = threadIdx.x;
    int row = tid >> 1, hf = tid & 1;

    uint32_t ka = arow[row] + k0 + hf * 16;
    uint32_t da = abase + (uint32_t)buf * (128 * 80) + (uint32_t)row * 80 + hf * 32;
    CPA16(da,      Ah + ka);
    CPA16(da + 16, Ah + ka + 8);

    uint32_t kb0 = brow[row]       + k0 + hf * 16;
    uint32_t kb1 = brow[row + 128] + k0 + hf * 16;
    uint32_t db = bbase + (uint32_t)buf * (256 * 80) + (uint32_t)row * 80 + hf * 32;
    CPA16(db,                 Bh + kb0);
    CPA16(db + 16,            Bh + kb0 + 8);
    CPA16(db + 128 * 80,      Bh + kb1);
    CPA16(db + 128 * 80 + 16, Bh + kb1 + 8);
    CPC();
}

// ======================= GEMM mainloop: CTA 128x256, warp 64x64 =======================
// K-stage 32, 3-buffer cp.async pipeline, ONE __syncthreads per stage.
// Fragment loads via ldmatrix.x4 (16/warp/stage instead of 64 scalar LDS).
__device__ __forceinline__ void mma_mainloop(
    char* smc,
    const __half* __restrict__ Ah, const __half* __restrict__ Bh,
    const uint32_t* __restrict__ arow, const uint32_t* __restrict__ brow,
    int S, float (&acc)[4][8][4])
{
    int tid  = threadIdx.x;
    int lane = tid & 31;
    int wid  = tid >> 5;
    int wm   = wid & 1;        // 2 m-groups of 64
    int wn   = wid >> 1;       // 4 n-groups of 64

    uint32_t abase = smem_u32(smc + OFF_A);
    uint32_t bbase = smem_u32(smc + OFF_B);

    // per-lane ldmatrix offset within a 16-row fragment block:
    // row = base + (lane & 15), k-half = (lane >> 4) * 16B
    uint32_t lm_off = (uint32_t)(lane & 15) * 80u + (uint32_t)(lane >> 4) * 16u;
    uint32_t a_off = abase + (uint32_t)(wm * 64) * 80u + lm_off;
    uint32_t b_off = bbase + (uint32_t)(wn * 64) * 80u + lm_off;

    load_stage(abase, bbase, Ah, Bh, arow, brow, 0,  0);
    load_stage(abase, bbase, Ah, Bh, arow, brow, 32, 1);

    int bu = 0, bnx = 2;
    for (int s = 0; s < S; s++) {
        CPW(1);
        __syncthreads();
        if (s + 2 < S)
            load_stage(abase, bbase, Ah, Bh, arow, brow, (s + 2) * 32, bnx);
        else
            CPC();   // keep group accounting uniform

        uint32_t abuf = a_off + (uint32_t)bu * (128 * 80);
        uint32_t bbuf = b_off + (uint32_t)bu * (256 * 80);
#pragma unroll
        for (int kc = 0; kc < 2; kc++) {
            uint32_t koff = (uint32_t)kc * 32u;
            // B: 4 x ldmatrix.x4, each covers 16 n-rows x 16 k
            uint32_t bfr[4][4];
#pragma unroll
            for (int g = 0; g < 4; g++)
                ldsm4(bfr[g], bbuf + (uint32_t)(g * 16) * 80u + koff);
#pragma unroll
            for (int mt = 0; mt < 4; mt++) {
                uint32_t ah[4];
                ldsm4(ah, abuf + (uint32_t)(mt * 16) * 80u + koff);
#pragma unroll
                for (int nt = 0; nt < 8; nt++) {
                    // group g = nt>>1; even nt -> matrices (0,2); odd -> (1,3)
                    uint32_t bb[2] = { bfr[nt >> 1][nt & 1], bfr[nt >> 1][(nt & 1) + 2] };
                    mma_f16(acc[mt][nt], ah, bb);
                }
            }
        }
        bu = (bu == 2) ? 0 : bu + 1;
        bnx = (bnx == 2) ? 0 : bnx + 1;
    }
    __syncthreads();   // all compute done before smem reuse
}

// ======================= GEMM1: h = relu(x @ w1 + b1) =======================
__global__ void __launch_bounds__(256)
gemm1_mma(const float* __restrict__ b1) {
    int e = blockIdx.z;
    int ce = g_count[e];
    int m0 = blockIdx.y * 128;
    if (m0 >= ce) return;
    int n0 = blockIdx.x * 256;
    int off = g_off[e];

    extern __shared__ char smc[];
    uint32_t* s_arow = (uint32_t*)(smc + OFF_AROW);
    uint32_t* s_brow = (uint32_t*)(smc + OFF_BROW);

    int tid = threadIdx.x;
    if (tid < 128) {
        int tok = (m0 + tid < ce) ? g_tok[e * N_TOK + m0 + tid] : 0;
        s_arow[tid] = (uint32_t)tok * DIM;
    }
    s_brow[tid] = (uint32_t)(e * HID + n0 + tid) * DIM;
    __syncthreads();

    float acc[4][8][4];
#pragma unroll
    for (int i = 0; i < 4; i++)
#pragma unroll
        for (int j = 0; j < 8; j++)
#pragma unroll
            for (int k = 0; k < 4; k++) acc[i][j][k] = 0.f;

    mma_mainloop(smc, g_xh, g_w1h, s_arow, s_brow, DIM / 32, acc);

    // epilogue: bias + relu -> stage 16x64 fp16 tile in smem -> coalesced 16B stores
    int lane = tid & 31, wid = tid >> 5;
    int wm = wid & 1, wn = wid >> 1;
    int r = lane >> 2, q = lane & 3;
    __half* stg = (__half*)(smc + OFF_A) + (size_t)wid * 1152;  // 16 rows x 72
    const float* brow_b1 = b1 + e * HID + n0 + wn * 64;
    int lr2 = lane >> 1, half2 = lane & 1;

#pragma unroll
    for (int mt = 0; mt < 4; mt++) {
#pragma unroll
        for (int rh = 0; rh < 2; rh++) {
            int lr = r + rh * 8;
#pragma unroll
            for (int nt = 0; nt < 8; nt++) {
                int lc = nt * 8 + 2 * q;
                float f0 = fmaxf(acc[mt][nt][rh * 2 + 0] + brow_b1[lc],     0.f);
                float f1 = fmaxf(acc[mt][nt][rh * 2 + 1] + brow_b1[lc + 1], 0.f);
                uint32_t ph = (uint32_t)__half_as_ushort(__float2half_rn(f0))
                            | ((uint32_t)__half_as_ushort(__float2half_rn(f1)) << 16);
                *(uint32_t*)(stg + lr * 72 + lc) = ph;
            }
        }
        __syncwarp();
        int grow = wm * 64 + mt * 16 + lr2;
        if (m0 + grow < ce) {
            size_t slot = (size_t)(off + m0 + grow);
            __half* dst = g_hh + slot * HID + n0 + wn * 64 + half2 * 32;
            const __half* srcp = stg + lr2 * 72 + half2 * 32;
#pragma unroll
            for (int c = 0; c < 4; c++)
                *(uint4*)(dst + c * 8) = *(const uint4*)(srcp + c * 8);
        }
        __syncwarp();
    }
}

// ======================= GEMM2: out += gate * (h @ w2 + b2) =======================
// Two m-tiles per CTA (R13 config, best measured).
__global__ void __launch_bounds__(256)
gemm2_mma(const float* __restrict__ b2, float* __restrict__ out) {
    int e = blockIdx.z;
    int ce = g_count[e];
    int n0 = blockIdx.x * 256;
    int off = g_off[e];

    extern __shared__ char smc[];
    uint32_t* s_arow = (uint32_t*)(smc + OFF_AROW);
    uint32_t* s_brow = (uint32_t*)(smc + OFF_BROW);

    int tid = threadIdx.x;
    int lane = tid & 31, wid = tid >> 5;
    int wm = wid & 1, wn = wid >> 1;
    int r = lane >> 2, q = lane & 3;

    s_brow[tid] = (uint32_t)(e * DIM + n0 + tid) * HID;

#pragma unroll 1
    for (int mi = 0; mi < 2; mi++) {
        int m0 = (blockIdx.y * 2 + mi) * 128;
        if (m0 >= ce) break;

        __syncthreads();   // brow store (mi=0) / prior tile fully done (mi=1)
        if (tid < 128) {
            int sl = off + m0 + tid;
            if (sl > 2 * N_TOK - 1) sl = 2 * N_TOK - 1;
            s_arow[tid] = (uint32_t)sl * HID;
        }
        __syncthreads();

        float acc[4][8][4];
#pragma unroll
        for (int i = 0; i < 4; i++)
#pragma unroll
            for (int j = 0; j < 8; j++)
#pragma unroll
                for (int k = 0; k < 4; k++) acc[i][j][k] = 0.f;

        mma_mainloop(smc, g_hh, g_w2h, s_arow, s_brow, HID / 32, acc);

        // epilogue: gate-weighted atomic add
#pragma unroll
        for (int mt = 0; mt < 4; mt++) {
#pragma unroll
            for (int rh = 0; rh < 2; rh++) {
                int row = wm * 64 + mt * 16 + r + rh * 8;
                if (m0 + row >= ce) continue;
                int slot2 = e * N_TOK + m0 + row;
                int tok = g_tok[slot2];
                float gw = g_gate[slot2];
                float* ob = out + (size_t)tok * DIM;
#pragma unroll
                for (int nt = 0; nt < 8; nt++) {
                    int col = n0 + wn * 64 + nt * 8 + 2 * q;
                    float f0 = acc[mt][nt][rh * 2 + 0] + b2[e * DIM + col];
                    float f1 = acc[mt][nt][rh * 2 + 1] + b2[e * DIM + col + 1];
                    atomicAdd(ob + col,     gw * f0);
                    atomicAdd(ob + col + 1, gw * f1);
                }
            }
        }
    }
}

// ======================= aux =======================
__global__ void aux_kernel(float* __restrict__ out, int out_size) {
    if (threadIdx.x == 0 && out_size >= N_TOK * DIM + 2) {
        float ent = g_ent / (float)N_TOK;
        float lb = 0.f;
#pragma unroll
        for (int e = 0; e < NE; e++) {
            float d = g_imp[e] / (float)N_TOK - 1.f / (float)NE;
            lb += d * d;
        }
        lb /= (float)NE;
        out[N_TOK * DIM]     = ent;
        out[N_TOK * DIM + 1] = lb;
    }
}

// ======================= launch (single stream) =======================
extern "C" void kernel_launch(void* const* d_in, const int* in_sizes, int n_in,
                              void* d_out, int out_size) {
    const float* x  = (const float*)d_in[0];
    const float* rw = (const float*)d_in[1];
    const float* rb = (const float*)d_in[2];
    const float* w1 = (const float*)d_in[3];
    const float* b1 = (const float*)d_in[4];
    const float* w2 = (const float*)d_in[5];
    const float* b2 = (const float*)d_in[6];
    float* out = (float*)d_out;

    cudaFuncSetAttribute(gemm1_mma, cudaFuncAttributeMaxDynamicSharedMemorySize, SMEM_TOTAL);
    cudaFuncSetAttribute(gemm2_mma, cudaFuncAttributeMaxDynamicSharedMemorySize, SMEM_TOTAL);

    cudaMemsetAsync(d_out, 0, (size_t)out_size * sizeof(float), 0);
    zero_kernel<<<1, 32>>>();
    router_kernel<<<N_TOK / 8, 256>>>(x, rw, rb);
    offsets_kernel<<<1, 1>>>();
    convert_x_kernel<<<(N_TOK * DIM) / 1024, 256>>>(x);
    {
        dim3 g(HID / 32, DIM / 32, NE);
        transpose_convert_kernel<<<g, 256>>>(w1, 0, DIM, HID);
    }
    {
        dim3 g(DIM / 32, HID / 32, NE);
        transpose_convert_kernel<<<g, 256>>>(w2, 1, HID, DIM);
    }

    {
        dim3 g(HID / 256, N_TOK / 128, NE);
        gemm1_mma<<<g, 256, SMEM_TOTAL>>>(b1);
    }
    {
        dim3 g(DIM / 256, N_TOK / 256, NE);   // 2 m-tiles per CTA
        gemm2_mma<<<g, 256, SMEM_TOTAL>>>(b2, out);
    }
    aux_kernel<<<1, 1>>>(out, out_size);
}

// round 17
// speedup vs baseline: 1.0886x; 1.0694x over previous
#include <cuda_runtime.h>
#include <cuda_fp16.h>
#include <math.h>
#include <stdint.h>

#define N_TOK 8192
#define DIM   1024
#define HID   4096
#define NE    8

// dynamic smem layout (bytes). Rows are 80B (64B data + 16B pad):
// cp.async-aligned (80 = 5*16) and gather words 20r+q mod 32 are a permutation.
#define OFF_A    0          // [3][128][20] u32 = 30720 (reused as h-staging post-loop)
#define OFF_B    30720      // [3][256][20] u32 = 61440
#define OFF_AROW 92160      // 128 u32
#define OFF_BROW 92672      // 256 u32
#define SMEM_TOTAL 93696

// ======================= PTX helpers =======================
__device__ __forceinline__ uint32_t smem_u32(const void* p) {
    uint32_t a;
    asm("{ .reg .u64 t; cvta.to.shared.u64 t, %1; cvt.u32.u64 %0, t; }" : "=r"(a) : "l"(p));
    return a;
}
#define CPA16(s, g) asm volatile("cp.async.cg.shared.global [%0], [%1], 16;" :: "r"(s), "l"(g))
#define CPC()       asm volatile("cp.async.commit_group;" ::: "memory")
#define CPW(n)      asm volatile("cp.async.wait_group %0;" :: "n"(n) : "memory")

__device__ __forceinline__ void mma_f16(float* d, const uint32_t* a, const uint32_t* b) {
    asm volatile("mma.sync.aligned.m16n8k16.row.col.f32.f16.f16.f32 "
                 "{%0,%1,%2,%3},{%4,%5,%6,%7},{%8,%9},{%0,%1,%2,%3};"
                 : "+f"(d[0]), "+f"(d[1]), "+f"(d[2]), "+f"(d[3])
                 : "r"(a[0]), "r"(a[1]), "r"(a[2]), "r"(a[3]), "r"(b[0]), "r"(b[1]));
}

// ======================= device scratch =======================
__device__ int   g_count[NE];
__device__ int   g_off[NE];
__device__ int   g_tok[NE * N_TOK];
__device__ float g_gate[NE * N_TOK];
__device__ float g_ent;
__device__ float g_imp[NE];

__device__ __align__(16) __half g_xh[(size_t)N_TOK * DIM];
__device__ __align__(16) __half g_w1h[(size_t)NE * HID * DIM];   // [e][n(hid)][k(dim)]
__device__ __align__(16) __half g_w2h[(size_t)NE * DIM * HID];   // [e][n(dim)][k(hid)]
__device__ __align__(16) __half g_hh[(size_t)2 * N_TOK * HID];   // [slot][hid]

// ======================= small kernels =======================
__global__ void zero_kernel() {
    int t = threadIdx.x;
    if (t < NE) { g_count[t] = 0; g_imp[t] = 0.f; }
    if (t == 0) g_ent = 0.f;
}

__global__ void router_kernel(const float* __restrict__ x,
                              const float* __restrict__ rw,
                              const float* __restrict__ rb) {
    __shared__ float s_ent[8];
    __shared__ float s_imp[8][NE];
    int warp = threadIdx.x >> 5;
    int lane = threadIdx.x & 31;
    int t = blockIdx.x * 8 + warp;

    float acc[NE];
#pragma unroll
    for (int e = 0; e < NE; e++) acc[e] = 0.f;
    const float* xr = x + (size_t)t * DIM;
    for (int k = lane; k < DIM; k += 32) {
        float xv = xr[k];
        const float* rwk = rw + k * NE;
#pragma unroll
        for (int e = 0; e < NE; e++) acc[e] += xv * rwk[e];
    }
#pragma unroll
    for (int e = 0; e < NE; e++)
#pragma unroll
        for (int s = 16; s > 0; s >>= 1)
            acc[e] += __shfl_xor_sync(0xffffffff, acc[e], s);

    if (lane == 0) {
        float lg[NE], m = -1e30f;
#pragma unroll
        for (int e = 0; e < NE; e++) { lg[e] = acc[e] + rb[e]; m = fmaxf(m, lg[e]); }
        float p[NE], sum = 0.f;
#pragma unroll
        for (int e = 0; e < NE; e++) { p[e] = expf(lg[e] - m); sum += p[e]; }
        float inv = 1.f / sum, ent = 0.f;
#pragma unroll
        for (int e = 0; e < NE; e++) {
            float pe = p[e] * inv;
            ent -= pe * logf(fmaxf(pe, 1e-8f));
            s_imp[warp][e] = pe;
        }
        s_ent[warp] = ent;
        int e0 = 0;
#pragma unroll
        for (int e = 1; e < NE; e++) if (lg[e] > lg[e0]) e0 = e;
        int e1 = (e0 == 0) ? 1 : 0;
#pragma unroll
        for (int e = 0; e < NE; e++) if (e != e0 && lg[e] > lg[e1]) e1 = e;
        float g0 = 1.f / (1.f + expf(lg[e1] - lg[e0]));
        float g1 = 1.f - g0;
        int p0 = atomicAdd(&g_count[e0], 1);
        g_tok [e0 * N_TOK + p0] = t; g_gate[e0 * N_TOK + p0] = g0;
        int p1 = atomicAdd(&g_count[e1], 1);
        g_tok [e1 * N_TOK + p1] = t; g_gate[e1 * N_TOK + p1] = g1;
    }
    __syncthreads();
    if (threadIdx.x < NE) {
        float se = 0.f;
#pragma unroll
        for (int w = 0; w < 8; w++) se += s_imp[w][threadIdx.x];
        atomicAdd(&g_imp[threadIdx.x], se);
    }
    if (threadIdx.x == 0) {
        float se = 0.f;
#pragma unroll
        for (int w = 0; w < 8; w++) se += s_ent[w];
        atomicAdd(&g_ent, se);
    }
}

__global__ void offsets_kernel() {
    if (threadIdx.x == 0) {
        int s = 0;
#pragma unroll
        for (int e = 0; e < NE; e++) { g_off[e] = s; s += g_count[e]; }
    }
}

__global__ void convert_x_kernel(const float* __restrict__ x) {
    size_t i = ((size_t)blockIdx.x * 256 + threadIdx.x) * 4;
    float4 v = *(const float4*)(x + i);
    uint32_t p0 = (uint32_t)__half_as_ushort(__float2half_rn(v.x))
                | ((uint32_t)__half_as_ushort(__float2half_rn(v.y)) << 16);
    uint32_t p1 = (uint32_t)__half_as_ushort(__float2half_rn(v.z))
                | ((uint32_t)__half_as_ushort(__float2half_rn(v.w)) << 16);
    *(uint2*)(g_xh + i) = make_uint2(p0, p1);
}

// transpose: src [e][R][C] fp32 -> INTERNAL dst [e][C][R] fp16.
// 32x64 tile, 8 elems/thread both phases (latency-bound -> more ILP).
// which=0 -> g_w1h ; which=1 -> g_w2h   (never pass device globals as host args)
__global__ void transpose_convert_kernel(const float* __restrict__ src,
                                         int which, int R, int C) {
    __shared__ float t[32][65];
    __half* dh = which ? g_w2h : g_w1h;
    int e = blockIdx.z;
    int c0 = blockIdx.x * 64, r0 = blockIdx.y * 32;
    const float* s = src + (size_t)e * R * C;
    int tid = threadIdx.x;

    // load: 32 rows x 64 cols; thread covers col (tid&63), rows (tid>>6)+4i
    int lc = tid & 63, lr = tid >> 6;
#pragma unroll
    for (int i = 0; i < 8; i++) {
        int row = lr + i * 4;
        t[row][lc] = s[(size_t)(r0 + row) * C + c0 + lc];
    }
    __syncthreads();

    // store: thread covers output col co = tid>>2 (0..63), rows rg..rg+7
    int co = tid >> 2, rg = (tid & 3) * 8;
    uint32_t pk[4];
#pragma unroll
    for (int j = 0; j < 4; j++) {
        __half h0 = __float2half_rn(t[rg + 2 * j][co]);
        __half h1 = __float2half_rn(t[rg + 2 * j + 1][co]);
        pk[j] = (uint32_t)__half_as_ushort(h0) | ((uint32_t)__half_as_ushort(h1) << 16);
    }
    size_t o = (size_t)e * R * C + (size_t)(c0 + co) * R + r0 + rg;
    *(uint4*)(dh + o) = make_uint4(pk[0], pk[1], pk[2], pk[3]);
}

// ======================= cp.async stage loader (K-chunk 32 = 64B/row) =======================
__device__ __forceinline__ void load_stage(
    uint32_t abase, uint32_t bbase,
    const __half* __restrict__ Ah, const __half* __restrict__ Bh,
    const uint32_t* __restrict__ arow, const uint32_t* __restrict__ brow,
    int k0, int buf)
{
    int tid = threadIdx.x;
    int row = tid >> 1, hf = tid & 1;

    uint32_t ka = arow[row] + k0 + hf * 16;
    uint32_t da = abase + (uint32_t)buf * (128 * 80) + (uint32_t)row * 80 + hf * 32;
    CPA16(da,      Ah + ka);
    CPA16(da + 16, Ah + ka + 8);

    uint32_t kb0 = brow[row]       + k0 + hf * 16;
    uint32_t kb1 = brow[row + 128] + k0 + hf * 16;
    uint32_t db = bbase + (uint32_t)buf * (256 * 80) + (uint32_t)row * 80 + hf * 32;
    CPA16(db,                 Bh + kb0);
    CPA16(db + 16,            Bh + kb0 + 8);
    CPA16(db + 128 * 80,      Bh + kb1);
    CPA16(db + 128 * 80 + 16, Bh + kb1 + 8);
    CPC();
}

// ======================= GEMM mainloop: CTA 128x256, warp 64x64 =======================
// K-stage 32, 3-buffer cp.async pipeline, ONE __syncthreads per stage.
__device__ __forceinline__ void mma_mainloop(
    char* smc,
    const __half* __restrict__ Ah, const __half* __restrict__ Bh,
    const uint32_t* __restrict__ arow, const uint32_t* __restrict__ brow,
    int S, float (&acc)[4][8][4])
{
    int tid  = threadIdx.x;
    int lane = tid & 31;
    int wid  = tid >> 5;
    int wm   = wid & 1;        // 2 m-groups of 64
    int wn   = wid >> 1;       // 4 n-groups of 64
    int q    = lane & 3;
    int r4   = lane >> 2;

    uint32_t (*A)[128][20] = (uint32_t (*)[128][20])(smc + OFF_A);
    uint32_t (*B)[256][20] = (uint32_t (*)[256][20])(smc + OFF_B);
    uint32_t abase = smem_u32(&A[0][0][0]);
    uint32_t bbase = smem_u32(&B[0][0][0]);

    load_stage(abase, bbase, Ah, Bh, arow, brow, 0,  0);
    load_stage(abase, bbase, Ah, Bh, arow, brow, 32, 1);

    int bu = 0, bnx = 2;
    for (int s = 0; s < S; s++) {
        CPW(1);
        __syncthreads();
        if (s + 2 < S)
            load_stage(abase, bbase, Ah, Bh, arow, brow, (s + 2) * 32, bnx);
        else
            CPC();   // keep group accounting uniform

#pragma unroll
        for (int kc = 0; kc < 2; kc++) {
            int kq = kc * 8 + q;
            uint32_t bhf[8][2];
#pragma unroll
            for (int nt = 0; nt < 8; nt++) {
                int nb = wn * 64 + nt * 8 + r4;
                bhf[nt][0] = B[bu][nb][kq];
                bhf[nt][1] = B[bu][nb][kq + 4];
            }
#pragma unroll
            for (int mt = 0; mt < 4; mt++) {
                int ra = wm * 64 + mt * 16 + r4;
                uint32_t ah[4];
                ah[0] = A[bu][ra][kq];      ah[1] = A[bu][ra + 8][kq];
                ah[2] = A[bu][ra][kq + 4];  ah[3] = A[bu][ra + 8][kq + 4];
#pragma unroll
                for (int nt = 0; nt < 8; nt++)
                    mma_f16(acc[mt][nt], ah, bhf[nt]);
            }
        }
        bu = (bu == 2) ? 0 : bu + 1;
        bnx = (bnx == 2) ? 0 : bnx + 1;
    }
    __syncthreads();   // all compute done before smem reuse
}

// ======================= GEMM1: h = relu(x @ w1 + b1) =======================
__global__ void __launch_bounds__(256)
gemm1_mma(const float* __restrict__ b1) {
    int e = blockIdx.z;
    int ce = g_count[e];
    int m0 = blockIdx.y * 128;
    if (m0 >= ce) return;
    int n0 = blockIdx.x * 256;
    int off = g_off[e];

    extern __shared__ char smc[];
    uint32_t* s_arow = (uint32_t*)(smc + OFF_AROW);
    uint32_t* s_brow = (uint32_t*)(smc + OFF_BROW);

    int tid = threadIdx.x;
    if (tid < 128) {
        int tok = (m0 + tid < ce) ? g_tok[e * N_TOK + m0 + tid] : 0;
        s_arow[tid] = (uint32_t)tok * DIM;
    }
    s_brow[tid] = (uint32_t)(e * HID + n0 + tid) * DIM;
    __syncthreads();

    float acc[4][8][4];
#pragma unroll
    for (int i = 0; i < 4; i++)
#pragma unroll
        for (int j = 0; j < 8; j++)
#pragma unroll
            for (int k = 0; k < 4; k++) acc[i][j][k] = 0.f;

    mma_mainloop(smc, g_xh, g_w1h, s_arow, s_brow, DIM / 32, acc);

    // epilogue: bias + relu -> stage 16x64 fp16 tile in smem -> coalesced 16B stores
    int lane = tid & 31, wid = tid >> 5;
    int wm = wid & 1, wn = wid >> 1;
    int r = lane >> 2, q = lane & 3;
    __half* stg = (__half*)(smc + OFF_A) + (size_t)wid * 1152;  // 16 rows x 72
    const float* brow_b1 = b1 + e * HID + n0 + wn * 64;
    int lr2 = lane >> 1, half2 = lane & 1;

#pragma unroll
    for (int mt = 0; mt < 4; mt++) {
#pragma unroll
        for (int rh = 0; rh < 2; rh++) {
            int lr = r + rh * 8;
#pragma unroll
            for (int nt = 0; nt < 8; nt++) {
                int lc = nt * 8 + 2 * q;
                float f0 = fmaxf(acc[mt][nt][rh * 2 + 0] + brow_b1[lc],     0.f);
                float f1 = fmaxf(acc[mt][nt][rh * 2 + 1] + brow_b1[lc + 1], 0.f);
                uint32_t ph = (uint32_t)__half_as_ushort(__float2half_rn(f0))
                            | ((uint32_t)__half_as_ushort(__float2half_rn(f1)) << 16);
                *(uint32_t*)(stg + lr * 72 + lc) = ph;
            }
        }
        __syncwarp();
        int grow = wm * 64 + mt * 16 + lr2;
        if (m0 + grow < ce) {
            size_t slot = (size_t)(off + m0 + grow);
            __half* dst = g_hh + slot * HID + n0 + wn * 64 + half2 * 32;
            const __half* srcp = stg + lr2 * 72 + half2 * 32;
#pragma unroll
            for (int c = 0; c < 4; c++)
                *(uint4*)(dst + c * 8) = *(const uint4*)(srcp + c * 8);
        }
        __syncwarp();
    }
}

// ======================= GEMM2: out += gate * (h @ w2 + b2) =======================
// Two m-tiles per CTA (R13 config, best measured).
__global__ void __launch_bounds__(256)
gemm2_mma(const float* __restrict__ b2, float* __restrict__ out) {
    int e = blockIdx.z;
    int ce = g_count[e];
    int n0 = blockIdx.x * 256;
    int off = g_off[e];

    extern __shared__ char smc[];
    uint32_t* s_arow = (uint32_t*)(smc + OFF_AROW);
    uint32_t* s_brow = (uint32_t*)(smc + OFF_BROW);

    int tid = threadIdx.x;
    int lane = tid & 31, wid = tid >> 5;
    int wm = wid & 1, wn = wid >> 1;
    int r = lane >> 2, q = lane & 3;

    s_brow[tid] = (uint32_t)(e * DIM + n0 + tid) * HID;

#pragma unroll 1
    for (int mi = 0; mi < 2; mi++) {
        int m0 = (blockIdx.y * 2 + mi) * 128;
        if (m0 >= ce) break;

        __syncthreads();   // brow store (mi=0) / prior tile fully done (mi=1)
        if (tid < 128) {
            int sl = off + m0 + tid;
            if (sl > 2 * N_TOK - 1) sl = 2 * N_TOK - 1;
            s_arow[tid] = (uint32_t)sl * HID;
        }
        __syncthreads();

        float acc[4][8][4];
#pragma unroll
        for (int i = 0; i < 4; i++)
#pragma unroll
            for (int j = 0; j < 8; j++)
#pragma unroll
                for (int k = 0; k < 4; k++) acc[i][j][k] = 0.f;

        mma_mainloop(smc, g_hh, g_w2h, s_arow, s_brow, HID / 32, acc);

        // epilogue: gate-weighted atomic add
#pragma unroll
        for (int mt = 0; mt < 4; mt++) {
#pragma unroll
            for (int rh = 0; rh < 2; rh++) {
                int row = wm * 64 + mt * 16 + r + rh * 8;
                if (m0 + row >= ce) continue;
                int slot2 = e * N_TOK + m0 + row;
                int tok = g_tok[slot2];
                float gw = g_gate[slot2];
                float* ob = out + (size_t)tok * DIM;
#pragma unroll
                for (int nt = 0; nt < 8; nt++) {
                    int col = n0 + wn * 64 + nt * 8 + 2 * q;
                    float f0 = acc[mt][nt][rh * 2 + 0] + b2[e * DIM + col];
                    float f1 = acc[mt][nt][rh * 2 + 1] + b2[e * DIM + col + 1];
                    atomicAdd(ob + col,     gw * f0);
                    atomicAdd(ob + col + 1, gw * f1);
                }
            }
        }
    }
}

// ======================= aux =======================
__global__ void aux_kernel(float* __restrict__ out, int out_size) {
    if (threadIdx.x == 0 && out_size >= N_TOK * DIM + 2) {
        float ent = g_ent / (float)N_TOK;
        float lb = 0.f;
#pragma unroll
        for (int e = 0; e < NE; e++) {
            float d = g_imp[e] / (float)N_TOK - 1.f / (float)NE;
            lb += d * d;
        }
        lb /= (float)NE;
        out[N_TOK * DIM]     = ent;
        out[N_TOK * DIM + 1] = lb;
    }
}

// ======================= launch (single stream) =======================
extern "C" void kernel_launch(void* const* d_in, const int* in_sizes, int n_in,
                              void* d_out, int out_size) {
    const float* x  = (const float*)d_in[0];
    const float* rw = (const float*)d_in[1];
    const float* rb = (const float*)d_in[2];
    const float* w1 = (const float*)d_in[3];
    const float* b1 = (const float*)d_in[4];
    const float* w2 = (const float*)d_in[5];
    const float* b2 = (const float*)d_in[6];
    float* out = (float*)d_out;

    cudaFuncSetAttribute(gemm1_mma, cudaFuncAttributeMaxDynamicSharedMemorySize, SMEM_TOTAL);
    cudaFuncSetAttribute(gemm2_mma, cudaFuncAttributeMaxDynamicSharedMemorySize, SMEM_TOTAL);

    cudaMemsetAsync(d_out, 0, (size_t)out_size * sizeof(float), 0);
    zero_kernel<<<1, 32>>>();
    router_kernel<<<N_TOK / 8, 256>>>(x, rw, rb);
    offsets_kernel<<<1, 1>>>();
    convert_x_kernel<<<(N_TOK * DIM) / 1024, 256>>>(x);
    {
        dim3 g(HID / 64, DIM / 32, NE);
        transpose_convert_kernel<<<g, 256>>>(w1, 0, DIM, HID);
    }
    {
        dim3 g(DIM / 64, HID / 32, NE);
        transpose_convert_kernel<<<g, 256>>>(w2, 1, HID, DIM);
    }

    {
        dim3 g(HID / 256, N_TOK / 128, NE);
        gemm1_mma<<<g, 256, SMEM_TOTAL>>>(b1);
    }
    {
        dim3 g(DIM / 256, N_TOK / 256, NE);   // 2 m-tiles per CTA
        gemm2_mma<<<g, 256, SMEM_TOTAL>>>(b2, out);
    }
    aux_kernel<<<1, 1>>>(out, out_size);
}